// round 1
// baseline (speedup 1.0000x reference)
#include <cuda_runtime.h>

// KANLinear fused as one GEMM:
//   A'[b, k*9+j] : j=0 -> silu(x[b,k]) ; j=1..8 -> cubic B-spline bases of x[b,k]
//   W'[n, k*9+j] : j=0 -> base_weight[n,k] ; j>0 -> spline_weight[n,k,j-1]*scaler[n,k]
//   out = A' @ W'^T   (K = 512*9 = 4608)

#define IN_F   512
#define OUT_F  512
#define NB     8          // GRID_SIZE + SPLINE_ORDER
#define KSLOT  9          // 1 base + 8 spline coeffs per in-feature
#define BATCH  16384

#define BM 128
#define BN 64
#define KC 4              // in-features per smem stage
#define KS (KC * KSLOT)   // 36 K-slots per stage

// Packed, pre-scaled weights, K-major for coalesced B-tile loads: [k*9+j][n]
__device__ float g_Wpack[IN_F * KSLOT * OUT_F];   // 9.44 MB

__global__ void prescale_kernel(const float* __restrict__ base_w,
                                const float* __restrict__ spline_w,
                                const float* __restrict__ scaler) {
    int idx = blockIdx.x * 256 + threadIdx.x;     // over OUT_F*IN_F
    if (idx >= OUT_F * IN_F) return;
    int n = idx / IN_F;
    int k = idx - n * IN_F;
    float sc = scaler[idx];
    g_Wpack[(k * KSLOT + 0) * OUT_F + n] = base_w[idx];
#pragma unroll
    for (int j = 0; j < NB; j++)
        g_Wpack[(k * KSLOT + 1 + j) * OUT_F + n] = spline_w[idx * NB + j] * sc;
}

__global__ __launch_bounds__(256)
void kan_gemm(const float* __restrict__ x,
              const float* __restrict__ grid,
              float* __restrict__ out) {
    __shared__ __align__(16) float As[KS * BM];   // [kslot][row]   18 KB
    __shared__ __align__(16) float Bs[KS * BN];   // [kslot][col]    9 KB
    __shared__ float rg[12];                      // knot vector
    __shared__ float rd1[11], rd2[10], rd3[9];    // reciprocal denominators

    const int tid = threadIdx.x;

    if (tid < 12) rg[tid] = grid[tid];
    __syncthreads();
    if (tid < 11)      { rd1[tid] = 1.0f / (rg[tid + 1] - rg[tid]); }
    else if (tid < 22) { int i = tid - 11; rd2[i] = 1.0f / (rg[i + 2] - rg[i]); }
    else if (tid < 31) { int i = tid - 22; rd3[i] = 1.0f / (rg[i + 3] - rg[i]); }
    // visibility handled by the __syncthreads at the top of the k0 loop

    const int m0 = blockIdx.y * BM;
    const int n0 = blockIdx.x * BN;
    const int tx = tid & 15;        // N:  16 * 4 = 64
    const int ty = tid >> 4;        // M:  16 * 8 = 128

    float acc[8][4];
#pragma unroll
    for (int i = 0; i < 8; i++)
#pragma unroll
        for (int j = 0; j < 4; j++) acc[i][j] = 0.0f;

    for (int k0 = 0; k0 < IN_F; k0 += KC) {
        __syncthreads();   // previous stage's readers done; also fences rd init

        // ---- Build A-tile: silu + B-spline bases on the fly ----
#pragma unroll
        for (int it = 0; it < (BM * KC) / 256; it++) {   // 2 iterations
            int idx = tid + it * 256;
            int row = idx & (BM - 1);
            int kk  = idx >> 7;                           // 0..KC-1
            float xv = x[(size_t)(m0 + row) * IN_F + k0 + kk];

            float s = xv / (1.0f + __expf(-xv));          // silu

            // Cox-de Boor, degree 0 -> 3 (matches reference exactly)
            float b0[11];
#pragma unroll
            for (int i = 0; i < 11; i++)
                b0[i] = (xv >= rg[i] && xv < rg[i + 1]) ? 1.0f : 0.0f;
            float b1[10];
#pragma unroll
            for (int i = 0; i < 10; i++)
                b1[i] = (xv - rg[i]) * rd1[i] * b0[i]
                      + (rg[i + 2] - xv) * rd1[i + 1] * b0[i + 1];
            float b2[9];
#pragma unroll
            for (int i = 0; i < 9; i++)
                b2[i] = (xv - rg[i]) * rd2[i] * b1[i]
                      + (rg[i + 3] - xv) * rd2[i + 1] * b1[i + 1];
            float b3[8];
#pragma unroll
            for (int i = 0; i < 8; i++)
                b3[i] = (xv - rg[i]) * rd3[i] * b2[i]
                      + (rg[i + 4] - xv) * rd3[i + 1] * b2[i + 1];

            float* ap = &As[kk * KSLOT * BM + row];
            ap[0] = s;
#pragma unroll
            for (int j = 0; j < NB; j++) ap[(1 + j) * BM] = b3[j];
        }

        // ---- Load B-tile (coalesced: K-major packed weights) ----
#pragma unroll
        for (int it = 0; it < (KS * BN) / 256; it++) {    // 9 iterations
            int idx = tid + it * 256;
            int col = idx & (BN - 1);
            int ks  = idx >> 6;
            Bs[ks * BN + col] = g_Wpack[(size_t)(k0 * KSLOT + ks) * OUT_F + n0 + col];
        }
        __syncthreads();

        // ---- Inner product over 36 K-slots ----
#pragma unroll
        for (int ks = 0; ks < KS; ks++) {
            float4 a0 = *(const float4*)&As[ks * BM + ty * 8];
            float4 a1 = *(const float4*)&As[ks * BM + ty * 8 + 4];
            float4 bv = *(const float4*)&Bs[ks * BN + tx * 4];
            float a[8] = {a0.x, a0.y, a0.z, a0.w, a1.x, a1.y, a1.z, a1.w};
            float b[4] = {bv.x, bv.y, bv.z, bv.w};
#pragma unroll
            for (int i = 0; i < 8; i++)
#pragma unroll
                for (int j = 0; j < 4; j++)
                    acc[i][j] += a[i] * b[j];
        }
    }

    // ---- Epilogue ----
#pragma unroll
    for (int i = 0; i < 8; i++) {
        float4 v = make_float4(acc[i][0], acc[i][1], acc[i][2], acc[i][3]);
        *(float4*)&out[(size_t)(m0 + ty * 8 + i) * OUT_F + n0 + tx * 4] = v;
    }
}

extern "C" void kernel_launch(void* const* d_in, const int* in_sizes, int n_in,
                              void* d_out, int out_size) {
    const float* x      = (const float*)d_in[0];
    const float* bw     = (const float*)d_in[1];
    const float* sw     = (const float*)d_in[2];
    const float* sc     = (const float*)d_in[3];
    const float* grid   = (const float*)d_in[4];
    float*       out    = (float*)d_out;

    prescale_kernel<<<(OUT_F * IN_F + 255) / 256, 256>>>(bw, sw, sc);

    dim3 g(OUT_F / BN, BATCH / BM);   // 8 x 128 = 1024 blocks
    kan_gemm<<<g, 256>>>(x, grid, out);
}

// round 3
// speedup vs baseline: 1.5860x; 1.5860x over previous
#include <cuda_runtime.h>
#include <cuda_bf16.h>
#include <cstdint>

#define IN_F   512
#define OUT_F  512
#define BATCH  16384
#define BM     128
#define BN     256
#define BK     64
#define NCH    88      // compute chunks: 8 silu_hi + 8 silu_lo + 8 silu_hi(x Wlo) + 64 spline
#define NST    80      // stored W chunks: 8 Whi_base + 8 Wlo_base + 64 spline Whi
#define TA     (BM * BK * 2)   // 16384
#define TB     (BN * BK * 2)   // 32768
#define DYN    (2 * TA + 2 * TB + 1024)

// Pre-packed, pre-swizzled bf16 weights: [st_chunk][n row: 64 bf16 = 128B, SW128]
__device__ __nv_bfloat16 g_W[(size_t)NST * OUT_F * BK];

// ---------------- helpers ----------------
static __device__ __forceinline__ uint32_t smem_u32(const void* p) {
    uint32_t a;
    asm("{ .reg .u64 t; cvta.to.shared.u64 t, %1; cvt.u32.u64 %0, t; }" : "=r"(a) : "l"(p));
    return a;
}
static __device__ __forceinline__ void cp16(uint32_t dst, const void* src) {
    asm volatile("cp.async.cg.shared.global [%0], [%1], 16;" :: "r"(dst), "l"(src) : "memory");
}
#define CP_COMMIT() asm volatile("cp.async.commit_group;" ::: "memory")
#define CP_WAIT1()  asm volatile("cp.async.wait_group 1;" ::: "memory")

static __device__ __forceinline__ void sts128(uint32_t a, uint32_t r0, uint32_t r1, uint32_t r2, uint32_t r3) {
    asm volatile("st.shared.v4.b32 [%0], {%1,%2,%3,%4};" :: "r"(a), "r"(r0), "r"(r1), "r"(r2), "r"(r3) : "memory");
}
static __device__ __forceinline__ void ldsm4(uint32_t* r, uint32_t a) {
    asm volatile("ldmatrix.sync.aligned.m8n8.x4.shared.b16 {%0,%1,%2,%3}, [%4];"
                 : "=r"(r[0]), "=r"(r[1]), "=r"(r[2]), "=r"(r[3]) : "r"(a));
}
static __device__ __forceinline__ void mma16816(float* d, const uint32_t* a, const uint32_t* b) {
    asm volatile("mma.sync.aligned.m16n8k16.row.col.f32.bf16.bf16.f32 "
                 "{%0,%1,%2,%3}, {%4,%5,%6,%7}, {%8,%9}, {%0,%1,%2,%3};"
                 : "+f"(d[0]), "+f"(d[1]), "+f"(d[2]), "+f"(d[3])
                 : "r"(a[0]), "r"(a[1]), "r"(a[2]), "r"(a[3]), "r"(b[0]), "r"(b[1]));
}
static __device__ __forceinline__ uint32_t pk2(float lo, float hi) {   // low half = lo
    uint32_t r; asm("cvt.rn.bf16x2.f32 %0, %1, %2;" : "=r"(r) : "f"(hi), "f"(lo)); return r;
}
static __device__ __forceinline__ uint32_t swz(uint32_t byteoff) {
    return byteoff ^ ((byteoff >> 3) & 0x70);
}
static __device__ __forceinline__ float bsel(int q, float p0, float p1, float p2, float p3) {
    return q == 0 ? p0 : q == 1 ? p1 : q == 2 ? p2 : q == 3 ? p3 : 0.0f;
}

// ---------------- weight packing ----------------
__global__ void pack_w(const float* __restrict__ bw, const float* __restrict__ sw,
                       const float* __restrict__ sc) {
    int idx = blockIdx.x * 256 + threadIdx.x;
    if (idx >= NST * OUT_F * BK) return;
    int st = idx >> 15;            // / 32768
    int r  = idx & 32767;
    int n = r >> 6, slot = r & 63;
    float w;
    if (st < 8) {
        w = bw[n * IN_F + st * 64 + slot];
    } else if (st < 16) {
        float ww = bw[n * IN_F + (st - 8) * 64 + slot];
        w = ww - __bfloat162float(__float2bfloat16_rn(ww));
    } else {
        int c = st - 16;
        int k = c * 8 + (slot >> 3), j = slot & 7;
        w = sw[((size_t)n * IN_F + k) * 8 + j] * sc[n * IN_F + k];
    }
    unsigned bo = (unsigned)(n * 128 + slot * 2);
    *(__nv_bfloat16*)((char*)g_W + (size_t)st * 65536 + swz(bo)) = __float2bfloat16_rn(w);
}

// ---------------- A-tile generation ----------------
static __device__ __forceinline__ void genA(int i, uint32_t Ab, const float* __restrict__ x,
                                            int m0, int tid, float g0, float invh) {
    if (i < 24) {
        const bool lo = (i >= 8 && i < 16);
        const int k0 = ((i < 8) ? i : (i < 16) ? i - 8 : i - 16) * 64;
#pragma unroll
        for (int it = 0; it < 4; it++) {
            int v = it * 256 + tid;
            int row = v >> 3, sg = v & 7;
            const float4* xp = (const float4*)(x + (size_t)(m0 + row) * IN_F + k0 + sg * 8);
            float4 xa = xp[0], xb = xp[1];
            float f[8] = {xa.x, xa.y, xa.z, xa.w, xb.x, xb.y, xb.z, xb.w};
            float s[8];
#pragma unroll
            for (int q = 0; q < 8; q++) {
                float sv = f[q] / (1.0f + __expf(-f[q]));
                if (lo) sv = sv - __bfloat162float(__float2bfloat16_rn(sv));
                s[q] = sv;
            }
            uint32_t a = Ab + swz((unsigned)(row * 128 + sg * 16));
            sts128(a, pk2(s[0], s[1]), pk2(s[2], s[3]), pk2(s[4], s[5]), pk2(s[6], s[7]));
        }
    } else {
        const int k0 = (i - 24) * 8;
#pragma unroll
        for (int it = 0; it < 4; it++) {
            int v = it * 256 + tid;
            int row = v >> 3, ff = v & 7;
            float xv = x[(size_t)(m0 + row) * IN_F + k0 + ff];
            float cf = (xv - g0) * invh;
            float cfl = floorf(cf);
            int ci = (int)cfl;
            float t = cf - cfl;
            // uniform cubic B-spline blending at local t
            float t2 = t * t, t3 = t2 * t;
            float u = 1.0f - t;
            float p0 = u * u * u * (1.0f / 6.0f);                       // basis ci-3
            float p1 = 0.5f * t3 - t2 + (2.0f / 3.0f);                  // basis ci-2
            float p2 = -0.5f * t3 + 0.5f * t2 + 0.5f * t + (1.0f / 6.0f); // basis ci-1
            float p3 = t3 * (1.0f / 6.0f);                              // basis ci
            int qb = 3 - ci;                   // q for basis index 0
            if (ci < 0 || ci > 10) qb = 100;   // outside knot span -> all zero
            uint32_t w0 = pk2(bsel(0 + qb, p0, p1, p2, p3), bsel(1 + qb, p0, p1, p2, p3));
            uint32_t w1 = pk2(bsel(2 + qb, p0, p1, p2, p3), bsel(3 + qb, p0, p1, p2, p3));
            uint32_t w2 = pk2(bsel(4 + qb, p0, p1, p2, p3), bsel(5 + qb, p0, p1, p2, p3));
            uint32_t w3 = pk2(bsel(6 + qb, p0, p1, p2, p3), bsel(7 + qb, p0, p1, p2, p3));
            uint32_t a = Ab + swz((unsigned)(row * 128 + ff * 16));
            sts128(a, w0, w1, w2, w3);
        }
    }
}

static __device__ __forceinline__ void loadB(int i, uint32_t Bb, int n0, int tid) {
    int st = (i < 8) ? i : i - 8;
    const char* src = (const char*)g_W + (size_t)st * 65536 + (size_t)n0 * 128;
#pragma unroll
    for (int it = 0; it < 8; it++) {
        int v = it * 256 + tid;
        cp16(Bb + v * 16, src + v * 16);
    }
}

// ---------------- main kernel ----------------
__global__ __launch_bounds__(256, 1)
void kan_mma(const float* __restrict__ x, const float* __restrict__ grid,
             float* __restrict__ out) {
    extern __shared__ char dynraw[];
    const int tid = threadIdx.x;
    const int m0 = blockIdx.y * BM;
    const int n0 = blockIdx.x * BN;

    uint32_t sbase = (smem_u32(dynraw) + 1023u) & ~1023u;
    const uint32_t A0 = sbase, A1 = sbase + TA;
    const uint32_t B0 = sbase + 2 * TA, B1 = sbase + 2 * TA + TB;

    const float g0 = grid[0];
    const float invh = 1.0f / (grid[1] - grid[0]);

    const int l = tid & 31, wid = tid >> 5;
    const int wm = wid & 1, wn = wid >> 1;

    // ldmatrix lane addressing (SW128: xor depends only on row&7)
    uint32_t offA[4], swzA[4];
#pragma unroll
    for (int mt = 0; mt < 4; mt++) {
        int rA = wm * 64 + mt * 16 + (l & 7) + (((l >> 3) & 1) << 3);
        offA[mt] = (uint32_t)(rA * 128);
        swzA[mt] = (uint32_t)((rA & 7) << 4);
    }
    const uint32_t colAsub = (uint32_t)((l >> 4) << 4);
    uint32_t offB[4], swzB[4];
#pragma unroll
    for (int nt2 = 0; nt2 < 4; nt2++) {
        int rB = wn * 64 + nt2 * 16 + (l & 7) + ((l >> 4) << 3);
        offB[nt2] = (uint32_t)(rB * 128);
        swzB[nt2] = (uint32_t)((rB & 7) << 4);
    }
    const uint32_t colBsub = (uint32_t)(((l >> 3) & 1) << 4);

    float acc[4][8][4];
#pragma unroll
    for (int a = 0; a < 4; a++)
#pragma unroll
        for (int b = 0; b < 8; b++)
#pragma unroll
            for (int c = 0; c < 4; c++) acc[a][b][c] = 0.0f;

    // prologue
    loadB(0, B0, n0, tid); CP_COMMIT();
    loadB(1, B1, n0, tid); CP_COMMIT();
    genA(0, A0, x, m0, tid, g0, invh);

    for (int i = 0; i < NCH; i++) {
        const uint32_t Ab = (i & 1) ? A1 : A0;
        const uint32_t Bb = (i & 1) ? B1 : B0;

        CP_WAIT1();          // B(i) arrived (B(i+1) may remain in flight)
        __syncthreads();     // A(i) generation complete, B(i) visible

#pragma unroll
        for (int ks = 0; ks < 4; ks++) {
            uint32_t af[4][4];
#pragma unroll
            for (int mt = 0; mt < 4; mt++)
                ldsm4(af[mt], Ab + offA[mt] + ((ks * 32 + colAsub) ^ swzA[mt]));
            uint32_t bf[8][2];
#pragma unroll
            for (int nt2 = 0; nt2 < 4; nt2++) {
                uint32_t r[4];
                ldsm4(r, Bb + offB[nt2] + ((ks * 32 + colBsub) ^ swzB[nt2]));
                bf[2 * nt2][0] = r[0]; bf[2 * nt2][1] = r[1];
                bf[2 * nt2 + 1][0] = r[2]; bf[2 * nt2 + 1][1] = r[3];
            }
#pragma unroll
            for (int mt = 0; mt < 4; mt++)
#pragma unroll
                for (int nt = 0; nt < 8; nt++)
                    mma16816(acc[mt][nt], af[mt], bf[nt]);
        }

        __syncthreads();     // everyone done reading A(i), B(i)

        if (i + 2 < NCH) loadB(i + 2, Bb, n0, tid);
        CP_COMMIT();         // commit (possibly empty) to keep group accounting uniform
        if (i + 1 < NCH) genA(i + 1, (i & 1) ? A0 : A1, x, m0, tid, g0, invh);
    }

    // epilogue: c-frag -> gmem (f32)
#pragma unroll
    for (int mt = 0; mt < 4; mt++) {
#pragma unroll
        for (int nt = 0; nt < 8; nt++) {
            int m = m0 + wm * 64 + mt * 16 + (l >> 2);
            int n = n0 + wn * 64 + nt * 8 + (l & 3) * 2;
            float2 v01 = make_float2(acc[mt][nt][0], acc[mt][nt][1]);
            float2 v23 = make_float2(acc[mt][nt][2], acc[mt][nt][3]);
            *(float2*)(out + (size_t)m * OUT_F + n) = v01;
            *(float2*)(out + (size_t)(m + 8) * OUT_F + n) = v23;
        }
    }
}

extern "C" void kernel_launch(void* const* d_in, const int* in_sizes, int n_in,
                              void* d_out, int out_size) {
    const float* x    = (const float*)d_in[0];
    const float* bw   = (const float*)d_in[1];
    const float* sw   = (const float*)d_in[2];
    const float* sc   = (const float*)d_in[3];
    const float* grid = (const float*)d_in[4];
    float*       out  = (float*)d_out;

    cudaFuncSetAttribute(kan_mma, cudaFuncAttributeMaxDynamicSharedMemorySize, DYN);

    pack_w<<<(NST * OUT_F * BK + 255) / 256, 256>>>(bw, sw, sc);

    dim3 g(OUT_F / BN, BATCH / BM);   // (2, 128) = 256 CTAs
    kan_mma<<<g, 256, DYN>>>(x, grid, out);
}

// round 4
// speedup vs baseline: 2.6589x; 1.6765x over previous
#include <cuda_runtime.h>
#include <cuda_bf16.h>
#include <cstdint>

#define IN_F   512
#define OUT_F  512
#define BATCH  16384
#define BM     128
#define BN     128
#define BK     64
#define NSTEP  88      // 24 base steps (8 kb x {hi*Whi, lo*Whi, hi*Wlo}) + 64 spline
#define NST    80      // stored W chunks: 8 Whi + 8 Wlo + 64 spline
#define TA     (BM * BK * 2)   // 16384
#define TB     (BN * BK * 2)   // 16384
#define DYN    (3 * TA + 3 * TB + 1024)

// Pre-packed, pre-swizzled bf16 weights: [st][n row: 64 bf16 = 128B, SW128]
__device__ __nv_bfloat16 g_W[(size_t)NST * OUT_F * BK];

// ---------------- helpers ----------------
static __device__ __forceinline__ uint32_t smem_u32(const void* p) {
    uint32_t a;
    asm("{ .reg .u64 t; cvta.to.shared.u64 t, %1; cvt.u32.u64 %0, t; }" : "=r"(a) : "l"(p));
    return a;
}
static __device__ __forceinline__ void cp16(uint32_t dst, const void* src) {
    asm volatile("cp.async.cg.shared.global [%0], [%1], 16;" :: "r"(dst), "l"(src) : "memory");
}
#define CP_COMMIT() asm volatile("cp.async.commit_group;" ::: "memory")
#define CP_WAIT1()  asm volatile("cp.async.wait_group 1;" ::: "memory")

static __device__ __forceinline__ void sts128(uint32_t a, uint32_t r0, uint32_t r1, uint32_t r2, uint32_t r3) {
    asm volatile("st.shared.v4.b32 [%0], {%1,%2,%3,%4};" :: "r"(a), "r"(r0), "r"(r1), "r"(r2), "r"(r3) : "memory");
}
static __device__ __forceinline__ void ldsm4(uint32_t* r, uint32_t a) {
    asm volatile("ldmatrix.sync.aligned.m8n8.x4.shared.b16 {%0,%1,%2,%3}, [%4];"
                 : "=r"(r[0]), "=r"(r[1]), "=r"(r[2]), "=r"(r[3]) : "r"(a));
}
static __device__ __forceinline__ void mma16816(float* d, const uint32_t* a, const uint32_t* b) {
    asm volatile("mma.sync.aligned.m16n8k16.row.col.f32.bf16.bf16.f32 "
                 "{%0,%1,%2,%3}, {%4,%5,%6,%7}, {%8,%9}, {%0,%1,%2,%3};"
                 : "+f"(d[0]), "+f"(d[1]), "+f"(d[2]), "+f"(d[3])
                 : "r"(a[0]), "r"(a[1]), "r"(a[2]), "r"(a[3]), "r"(b[0]), "r"(b[1]));
}
static __device__ __forceinline__ uint32_t pk2(float lo, float hi) {
    uint32_t r; asm("cvt.rn.bf16x2.f32 %0, %1, %2;" : "=r"(r) : "f"(hi), "f"(lo)); return r;
}
static __device__ __forceinline__ uint32_t swz(uint32_t byteoff) {
    return byteoff ^ ((byteoff >> 3) & 0x70);
}
static __device__ __forceinline__ float bsel(int q, float p0, float p1, float p2, float p3) {
    return q == 0 ? p0 : q == 1 ? p1 : q == 2 ? p2 : q == 3 ? p3 : 0.0f;
}

// ---------------- weight packing ----------------
__global__ void pack_w(const float* __restrict__ bw, const float* __restrict__ sw,
                       const float* __restrict__ sc) {
    int idx = blockIdx.x * 256 + threadIdx.x;
    if (idx >= NST * OUT_F * BK) return;
    int st = idx >> 15;
    int r  = idx & 32767;
    int n = r >> 6, slot = r & 63;
    float w;
    if (st < 8) {
        w = bw[n * IN_F + st * 64 + slot];
    } else if (st < 16) {
        float ww = bw[n * IN_F + (st - 8) * 64 + slot];
        w = ww - __bfloat162float(__float2bfloat16_rn(ww));
    } else {
        int c = st - 16;
        int k = c * 8 + (slot >> 3), j = slot & 7;
        w = sw[((size_t)n * IN_F + k) * 8 + j] * sc[n * IN_F + k];
    }
    unsigned bo = (unsigned)(n * 128 + slot * 2);
    *(__nv_bfloat16*)((char*)g_W + (size_t)st * 65536 + swz(bo)) = __float2bfloat16_rn(w);
}

// ---------------- A-tile generation ----------------
static __device__ __forceinline__ void gen_silu(uint32_t Ab, const float* __restrict__ x,
                                                int m0, int tid, int kb, bool lo) {
    const int k0 = kb * 64;
#pragma unroll
    for (int it = 0; it < 4; it++) {
        int v = it * 256 + tid;
        int row = v >> 3, sg = v & 7;
        const float4* xp = (const float4*)(x + (size_t)(m0 + row) * IN_F + k0 + sg * 8);
        float4 xa = xp[0], xb = xp[1];
        float f[8] = {xa.x, xa.y, xa.z, xa.w, xb.x, xb.y, xb.z, xb.w};
        float s[8];
#pragma unroll
        for (int q = 0; q < 8; q++) {
            float sv = f[q] / (1.0f + __expf(-f[q]));
            if (lo) sv = sv - __bfloat162float(__float2bfloat16_rn(sv));
            s[q] = sv;
        }
        uint32_t a = Ab + swz((unsigned)(row * 128 + sg * 16));
        sts128(a, pk2(s[0], s[1]), pk2(s[2], s[3]), pk2(s[4], s[5]), pk2(s[6], s[7]));
    }
}
static __device__ __forceinline__ void gen_spline(uint32_t Ab, const float* __restrict__ x,
                                                  int m0, int tid, int c, float g0, float invh) {
    const int k0 = c * 8;
#pragma unroll
    for (int it = 0; it < 4; it++) {
        int v = it * 256 + tid;
        int row = v >> 3, ff = v & 7;
        float xv = x[(size_t)(m0 + row) * IN_F + k0 + ff];
        float cf = (xv - g0) * invh;
        float cfl = floorf(cf);
        int ci = (int)cfl;
        float t = cf - cfl;
        float t2 = t * t, t3 = t2 * t;
        float u = 1.0f - t;
        float p0 = u * u * u * (1.0f / 6.0f);
        float p1 = 0.5f * t3 - t2 + (2.0f / 3.0f);
        float p2 = -0.5f * t3 + 0.5f * t2 + 0.5f * t + (1.0f / 6.0f);
        float p3 = t3 * (1.0f / 6.0f);
        int qb = 3 - ci;
        if (ci < 0 || ci > 10) qb = 100;
        uint32_t w0 = pk2(bsel(0 + qb, p0, p1, p2, p3), bsel(1 + qb, p0, p1, p2, p3));
        uint32_t w1 = pk2(bsel(2 + qb, p0, p1, p2, p3), bsel(3 + qb, p0, p1, p2, p3));
        uint32_t w2 = pk2(bsel(4 + qb, p0, p1, p2, p3), bsel(5 + qb, p0, p1, p2, p3));
        uint32_t w3 = pk2(bsel(6 + qb, p0, p1, p2, p3), bsel(7 + qb, p0, p1, p2, p3));
        uint32_t a = Ab + swz((unsigned)(row * 128 + ff * 16));
        sts128(a, w0, w1, w2, w3);
    }
}
static __device__ __forceinline__ void loadB(uint32_t Bb, int st, int n0, int tid) {
    const char* src = (const char*)g_W + (size_t)st * 65536 + (size_t)n0 * 128;
#pragma unroll
    for (int it = 0; it < 4; it++) {
        int v = it * 256 + tid;
        cp16(Bb + v * 16, src + v * 16);
    }
}

// slot maps (verified static schedule; A/B triple-buffered, slot = genIndex % 3)
static __device__ __forceinline__ int a_slot_of(int s) {
    if (s < 24) { int kb = s / 3, r = s - 3 * kb; return (r == 1 ? 2 * kb + 1 : 2 * kb) % 3; }
    return (s - 8) % 3;
}
static __device__ __forceinline__ int b_slot_of(int s) {
    if (s < 24) { int kb = s / 3, r = s - 3 * kb; return (r == 2 ? 2 * kb + 1 : 2 * kb) % 3; }
    return (s - 8) % 3;
}

// ---------------- main kernel ----------------
__global__ __launch_bounds__(256, 2)
void kan_mma(const float* __restrict__ x, const float* __restrict__ grid,
             float* __restrict__ out) {
    extern __shared__ char dynraw[];
    const int tid = threadIdx.x;
    const int m0 = blockIdx.y * BM;
    const int n0 = blockIdx.x * BN;

    uint32_t sbase = (smem_u32(dynraw) + 1023u) & ~1023u;
    const uint32_t Abase = sbase;
    const uint32_t Bbase = sbase + 3 * TA;

    const float g0 = grid[0];
    const float invh = 1.0f / (grid[1] - grid[0]);

    const int l = tid & 31, wid = tid >> 5;
    const int wm = wid & 1, wn = wid >> 1;     // 2 x 4 warps; warp tile 64 x 32

    uint32_t offA[4], swzA[4];
#pragma unroll
    for (int mt = 0; mt < 4; mt++) {
        int rA = wm * 64 + mt * 16 + (l & 7) + (((l >> 3) & 1) << 3);
        offA[mt] = (uint32_t)(rA * 128);
        swzA[mt] = (uint32_t)((rA & 7) << 4);
    }
    const uint32_t colAsub = (uint32_t)((l >> 4) << 4);
    uint32_t offB[2], swzB[2];
#pragma unroll
    for (int nt2 = 0; nt2 < 2; nt2++) {
        int rB = wn * 32 + nt2 * 16 + (l & 7) + ((l >> 4) << 3);
        offB[nt2] = (uint32_t)(rB * 128);
        swzB[nt2] = (uint32_t)((rB & 7) << 4);
    }
    const uint32_t colBsub = (uint32_t)(((l >> 3) & 1) << 4);

    float acc[4][4][4];
#pragma unroll
    for (int a = 0; a < 4; a++)
#pragma unroll
        for (int b = 0; b < 4; b++)
#pragma unroll
            for (int c = 0; c < 4; c++) acc[a][b][c] = 0.0f;

    // ---- prologue: gen Ahi(0) -> A slot0; load Whi(0) -> B slot0 (G0); empty G1
    gen_silu(Abase, x, m0, tid, 0, false);
    loadB(Bbase, 0, n0, tid); CP_COMMIT();
    CP_COMMIT();

    for (int s = 0; s < NSTEP; s++) {
        CP_WAIT1();
        __syncthreads();      // A(s) generated, B(s) arrived & visible

        const uint32_t Ab = Abase + a_slot_of(s) * TA;
        const uint32_t Bb = Bbase + b_slot_of(s) * TB;

#pragma unroll
        for (int ks = 0; ks < 4; ks++) {
            uint32_t af[4][4];
#pragma unroll
            for (int mt = 0; mt < 4; mt++)
                ldsm4(af[mt], Ab + offA[mt] + ((ks * 32 + colAsub) ^ swzA[mt]));
            uint32_t bf[4][2];
#pragma unroll
            for (int nt2 = 0; nt2 < 2; nt2++) {
                uint32_t r[4];
                ldsm4(r, Bb + offB[nt2] + ((ks * 32 + colBsub) ^ swzB[nt2]));
                bf[2 * nt2][0] = r[0]; bf[2 * nt2][1] = r[1];
                bf[2 * nt2 + 1][0] = r[2]; bf[2 * nt2 + 1][1] = r[3];
            }
#pragma unroll
            for (int mt = 0; mt < 4; mt++)
#pragma unroll
                for (int nt = 0; nt < 4; nt++)
                    mma16816(acc[mt][nt], af[mt], bf[nt]);
        }

        __syncthreads();      // everyone done reading A(s), B(s)

        // ---- issue B for step s+2, exactly one commit per step
        {
            int u = s + 2;
            if (u < 24) {
                int kb = u / 3, r = u - 3 * kb;
                if (r == 0)      loadB(Bbase + ((2 * kb) % 3) * TB, kb, n0, tid);
                else if (r == 2) loadB(Bbase + ((2 * kb + 1) % 3) * TB, 8 + kb, n0, tid);
                // r == 1: reuse, no load
            } else if (u <= 87) {
                int c = u - 24;
                loadB(Bbase + ((16 + c) % 3) * TB, 16 + c, n0, tid);
            }
            CP_COMMIT();
        }

        // ---- generate A for a future step (schedule: see slot proof)
        {
            int r3 = s - (s / 3) * 3;
            if (s < 24 && r3 == 0) {
                int kb = s / 3;   // gen Alo(kb), first used at s+1
                gen_silu(Abase + ((2 * kb + 1) % 3) * TA, x, m0, tid, kb, true);
            } else if (s < 22 && r3 == 1) {
                int kb = s / 3 + 1;   // gen Ahi(kb), first used at 3kb
                gen_silu(Abase + ((2 * kb) % 3) * TA, x, m0, tid, kb, false);
            } else if (s >= 23 && s <= 86) {
                int c = s - 23;       // gen Asp(c), first used at 24+c
                gen_spline(Abase + ((16 + c) % 3) * TA, x, m0, tid, c, g0, invh);
            }
        }
    }

    // ---- epilogue ----
#pragma unroll
    for (int mt = 0; mt < 4; mt++) {
#pragma unroll
        for (int nt = 0; nt < 4; nt++) {
            int m = m0 + wm * 64 + mt * 16 + (l >> 2);
            int n = n0 + wn * 32 + nt * 8 + (l & 3) * 2;
            *(float2*)(out + (size_t)m * OUT_F + n) = make_float2(acc[mt][nt][0], acc[mt][nt][1]);
            *(float2*)(out + (size_t)(m + 8) * OUT_F + n) = make_float2(acc[mt][nt][2], acc[mt][nt][3]);
        }
    }
}

extern "C" void kernel_launch(void* const* d_in, const int* in_sizes, int n_in,
                              void* d_out, int out_size) {
    const float* x    = (const float*)d_in[0];
    const float* bw   = (const float*)d_in[1];
    const float* sw   = (const float*)d_in[2];
    const float* sc   = (const float*)d_in[3];
    const float* grid = (const float*)d_in[4];
    float*       out  = (float*)d_out;

    cudaFuncSetAttribute(kan_mma, cudaFuncAttributeMaxDynamicSharedMemorySize, DYN);

    pack_w<<<(NST * OUT_F * BK + 255) / 256, 256>>>(bw, sw, sc);

    dim3 g(OUT_F / BN, BATCH / BM);   // (4, 128) = 512 CTAs
    kan_mma<<<g, 256, DYN>>>(x, grid, out);
}

// round 5
// speedup vs baseline: 5.5342x; 2.0814x over previous
#include <cuda_runtime.h>
#include <cuda_bf16.h>
#include <cstdint>

#define IN_F   512
#define OUT_F  512
#define BATCH  16384
#define BM     128
#define BN     128
#define BK     64
#define NSTEP  88      // 24 base steps (8 kb x {hi*Whi, lo*Whi, hi*Wlo}) + 64 spline
#define NST    80      // stored chunks: 8 hi/Whi + 8 lo/Wlo + 64 spline
#define TA     (BM * BK * 2)   // 16384
#define TB     (BN * BK * 2)   // 16384
#define DYN    (3 * TA + 3 * TB + 1024)   // 99328

// Pre-packed, pre-swizzled bf16 weights: [st][n row: 64 bf16 = 128B, SW128]
__device__ __nv_bfloat16 g_W[(size_t)NST * OUT_F * BK];
// Precomputed augmented A: [rowblock(128)][chunk(80)][row(128)][slot(64)] bf16, SW128 tiles
__device__ __nv_bfloat16 g_A[(size_t)128 * NST * BM * BK];   // 168 MB

// ---------------- helpers ----------------
static __device__ __forceinline__ uint32_t smem_u32(const void* p) {
    uint32_t a;
    asm("{ .reg .u64 t; cvta.to.shared.u64 t, %1; cvt.u32.u64 %0, t; }" : "=r"(a) : "l"(p));
    return a;
}
static __device__ __forceinline__ void cp16(uint32_t dst, const void* src) {
    asm volatile("cp.async.cg.shared.global [%0], [%1], 16;" :: "r"(dst), "l"(src) : "memory");
}
#define CP_COMMIT() asm volatile("cp.async.commit_group;" ::: "memory")
#define CP_WAIT1()  asm volatile("cp.async.wait_group 1;" ::: "memory")

static __device__ __forceinline__ void ldsm4(uint32_t* r, uint32_t a) {
    asm volatile("ldmatrix.sync.aligned.m8n8.x4.shared.b16 {%0,%1,%2,%3}, [%4];"
                 : "=r"(r[0]), "=r"(r[1]), "=r"(r[2]), "=r"(r[3]) : "r"(a));
}
static __device__ __forceinline__ void mma16816(float* d, const uint32_t* a, const uint32_t* b) {
    asm volatile("mma.sync.aligned.m16n8k16.row.col.f32.bf16.bf16.f32 "
                 "{%0,%1,%2,%3}, {%4,%5,%6,%7}, {%8,%9}, {%0,%1,%2,%3};"
                 : "+f"(d[0]), "+f"(d[1]), "+f"(d[2]), "+f"(d[3])
                 : "r"(a[0]), "r"(a[1]), "r"(a[2]), "r"(a[3]), "r"(b[0]), "r"(b[1]));
}
static __device__ __forceinline__ uint32_t pk2(float lo, float hi) {
    uint32_t r; asm("cvt.rn.bf16x2.f32 %0, %1, %2;" : "=r"(r) : "f"(hi), "f"(lo)); return r;
}
static __device__ __forceinline__ uint32_t swz(uint32_t byteoff) {
    return byteoff ^ ((byteoff >> 3) & 0x70);
}
static __device__ __forceinline__ float bsel(int q, float p0, float p1, float p2, float p3) {
    return q == 0 ? p0 : q == 1 ? p1 : q == 2 ? p2 : q == 3 ? p3 : 0.0f;
}

// ---------------- weight packing ----------------
__global__ void pack_w(const float* __restrict__ bw, const float* __restrict__ sw,
                       const float* __restrict__ sc) {
    int idx = blockIdx.x * 256 + threadIdx.x;
    if (idx >= NST * OUT_F * BK) return;
    int st = idx >> 15;
    int r  = idx & 32767;
    int n = r >> 6, slot = r & 63;
    float w;
    if (st < 8) {
        w = bw[n * IN_F + st * 64 + slot];
    } else if (st < 16) {
        float ww = bw[n * IN_F + (st - 8) * 64 + slot];
        w = ww - __bfloat162float(__float2bfloat16_rn(ww));
    } else {
        int c = st - 16;
        int k = c * 8 + (slot >> 3), j = slot & 7;
        w = sw[((size_t)n * IN_F + k) * 8 + j] * sc[n * IN_F + k];
    }
    unsigned bo = (unsigned)(n * 128 + slot * 2);
    *(__nv_bfloat16*)((char*)g_W + (size_t)st * 65536 + swz(bo)) = __float2bfloat16_rn(w);
}

// ---------------- A generation (one-shot, tiled+swizzled to global) ----------------
__global__ __launch_bounds__(256)
void gen_a(const float* __restrict__ x, const float* __restrict__ grid) {
    int idx = blockIdx.x * 256 + threadIdx.x;    // over 16384 * 64
    int m = idx >> 6, kg = idx & 63;
    int rb = m >> 7, row = m & 127;

    const float g0 = grid[0];
    const float invh = 1.0f / (grid[1] - grid[0]);

    const float4* xp = (const float4*)(x + (size_t)m * IN_F + kg * 8);
    float4 xa = xp[0], xb = xp[1];
    float f[8] = {xa.x, xa.y, xa.z, xa.w, xb.x, xb.y, xb.z, xb.w};

    char* base = (char*)g_A + ((size_t)rb * NST << 14);

    // silu hi / lo
    float shi[8], slo[8];
#pragma unroll
    for (int q = 0; q < 8; q++) {
        float sv = f[q] / (1.0f + __expf(-f[q]));
        shi[q] = sv;
        slo[q] = sv - __bfloat162float(__float2bfloat16_rn(sv));
    }
    unsigned offs = swz((unsigned)(row * 128 + (kg & 7) * 16));
    {
        uint4 vh = make_uint4(pk2(shi[0], shi[1]), pk2(shi[2], shi[3]),
                              pk2(shi[4], shi[5]), pk2(shi[6], shi[7]));
        uint4 vl = make_uint4(pk2(slo[0], slo[1]), pk2(slo[2], slo[3]),
                              pk2(slo[4], slo[5]), pk2(slo[6], slo[7]));
        *(uint4*)(base + ((size_t)(kg >> 3) << 14) + offs) = vh;
        *(uint4*)(base + ((size_t)(8 + (kg >> 3)) << 14) + offs) = vl;
    }

    // spline chunk 16+kg: this thread writes the full 128B row (8 feats x 8 bases)
    char* sp = base + ((size_t)(16 + kg) << 14);
#pragma unroll
    for (int ff = 0; ff < 8; ff++) {
        float xv = f[ff];
        float cf = (xv - g0) * invh;
        float cfl = floorf(cf);
        int ci = (int)cfl;
        float t = cf - cfl;
        float t2 = t * t, t3 = t2 * t;
        float u = 1.0f - t;
        float p0 = u * u * u * (1.0f / 6.0f);
        float p1 = 0.5f * t3 - t2 + (2.0f / 3.0f);
        float p2 = -0.5f * t3 + 0.5f * t2 + 0.5f * t + (1.0f / 6.0f);
        float p3 = t3 * (1.0f / 6.0f);
        int qb = 3 - ci;
        if (ci < 0 || ci > 10) qb = 100;
        uint4 v = make_uint4(
            pk2(bsel(0 + qb, p0, p1, p2, p3), bsel(1 + qb, p0, p1, p2, p3)),
            pk2(bsel(2 + qb, p0, p1, p2, p3), bsel(3 + qb, p0, p1, p2, p3)),
            pk2(bsel(4 + qb, p0, p1, p2, p3), bsel(5 + qb, p0, p1, p2, p3)),
            pk2(bsel(6 + qb, p0, p1, p2, p3), bsel(7 + qb, p0, p1, p2, p3)));
        *(uint4*)(sp + swz((unsigned)(row * 128 + ff * 16))) = v;
    }
}

// step -> (A chunk, W chunk)
static __device__ __forceinline__ void step_chunks(int s, int& aCh, int& bCh) {
    if (s < 24) {
        int kb = s / 3, r = s - 3 * kb;
        aCh = (r == 1) ? 8 + kb : kb;
        bCh = (r == 2) ? 8 + kb : kb;
    } else {
        aCh = bCh = 16 + (s - 24);
    }
}

// ---------------- main kernel: pure streaming GEMM ----------------
__global__ __launch_bounds__(256, 2)
void kan_mma(float* __restrict__ out) {
    extern __shared__ char dynraw[];
    const int tid = threadIdx.x;
    const int rb = blockIdx.y;
    const int m0 = rb * BM;
    const int n0 = blockIdx.x * BN;

    uint32_t sbase = (smem_u32(dynraw) + 1023u) & ~1023u;
    const uint32_t Abase = sbase;
    const uint32_t Bbase = sbase + 3 * TA;

    const int l = tid & 31, wid = tid >> 5;
    const int wm = wid & 1, wn = wid >> 1;     // warp tile 64 x 32

    uint32_t offA[4], swzA[4];
#pragma unroll
    for (int mt = 0; mt < 4; mt++) {
        int rA = wm * 64 + mt * 16 + (l & 7) + (((l >> 3) & 1) << 3);
        offA[mt] = (uint32_t)(rA * 128);
        swzA[mt] = (uint32_t)((rA & 7) << 4);
    }
    const uint32_t colAsub = (uint32_t)((l >> 4) << 4);
    uint32_t offB[2], swzB[2];
#pragma unroll
    for (int nt2 = 0; nt2 < 2; nt2++) {
        int rB = wn * 32 + nt2 * 16 + (l & 7) + ((l >> 4) << 3);
        offB[nt2] = (uint32_t)(rB * 128);
        swzB[nt2] = (uint32_t)((rB & 7) << 4);
    }
    const uint32_t colBsub = (uint32_t)(((l >> 3) & 1) << 4);

    const char* Aglob = (const char*)g_A + ((size_t)rb * NST << 14);
    const char* Bglob = (const char*)g_W + (size_t)n0 * 128;

    float acc[4][4][4];
#pragma unroll
    for (int a = 0; a < 4; a++)
#pragma unroll
        for (int b = 0; b < 4; b++)
#pragma unroll
            for (int c = 0; c < 4; c++) acc[a][b][c] = 0.0f;

    // prefetch loader: 16KB each, lanes contiguous 16B (dense 512B/warp/instr)
    auto loadAB = [&](int s, int buf) {
        int aCh, bCh;
        step_chunks(s, aCh, bCh);
        const char* As = Aglob + ((size_t)aCh << 14);
        const char* Bs = Bglob + ((size_t)bCh << 16);
        uint32_t Ad = Abase + buf * TA, Bd = Bbase + buf * TB;
#pragma unroll
        for (int it = 0; it < 4; it++) {
            cp16(Ad + tid * 16 + it * 4096, As + tid * 16 + it * 4096);
            cp16(Bd + tid * 16 + it * 4096, Bs + tid * 16 + it * 4096);
        }
    };

    loadAB(0, 0); CP_COMMIT();
    loadAB(1, 1); CP_COMMIT();

    for (int s = 0; s < NSTEP; s++) {
        CP_WAIT1();            // group(s) landed; group(s+1) may be in flight
        __syncthreads();       // all warps: done reading buffers of step s-1

        if (s + 2 < NSTEP) loadAB(s + 2, (s + 2) % 3);
        CP_COMMIT();           // exactly one group per step (possibly empty)

        const uint32_t Ab = Abase + (s % 3) * TA;
        const uint32_t Bb = Bbase + (s % 3) * TB;

#pragma unroll
        for (int ks = 0; ks < 4; ks++) {
            uint32_t af[4][4];
#pragma unroll
            for (int mt = 0; mt < 4; mt++)
                ldsm4(af[mt], Ab + offA[mt] + ((ks * 32 + colAsub) ^ swzA[mt]));
            uint32_t bf[4][2];
#pragma unroll
            for (int nt2 = 0; nt2 < 2; nt2++) {
                uint32_t r[4];
                ldsm4(r, Bb + offB[nt2] + ((ks * 32 + colBsub) ^ swzB[nt2]));
                bf[2 * nt2][0] = r[0]; bf[2 * nt2][1] = r[1];
                bf[2 * nt2 + 1][0] = r[2]; bf[2 * nt2 + 1][1] = r[3];
            }
#pragma unroll
            for (int mt = 0; mt < 4; mt++)
#pragma unroll
                for (int nt = 0; nt < 4; nt++)
                    mma16816(acc[mt][nt], af[mt], bf[nt]);
        }
    }

    // ---- epilogue ----
#pragma unroll
    for (int mt = 0; mt < 4; mt++) {
#pragma unroll
        for (int nt = 0; nt < 4; nt++) {
            int m = m0 + wm * 64 + mt * 16 + (l >> 2);
            int n = n0 + wn * 32 + nt * 8 + (l & 3) * 2;
            *(float2*)(out + (size_t)m * OUT_F + n) = make_float2(acc[mt][nt][0], acc[mt][nt][1]);
            *(float2*)(out + (size_t)(m + 8) * OUT_F + n) = make_float2(acc[mt][nt][2], acc[mt][nt][3]);
        }
    }
}

extern "C" void kernel_launch(void* const* d_in, const int* in_sizes, int n_in,
                              void* d_out, int out_size) {
    const float* x    = (const float*)d_in[0];
    const float* bw   = (const float*)d_in[1];
    const float* sw   = (const float*)d_in[2];
    const float* sc   = (const float*)d_in[3];
    const float* grid = (const float*)d_in[4];
    float*       out  = (float*)d_out;

    cudaFuncSetAttribute(kan_mma, cudaFuncAttributeMaxDynamicSharedMemorySize, DYN);

    pack_w<<<(NST * OUT_F * BK + 255) / 256, 256>>>(bw, sw, sc);
    gen_a<<<(BATCH * 64) / 256, 256>>>(x, grid);

    dim3 g(OUT_F / BN, BATCH / BM);   // (4, 128) = 512 CTAs
    kan_mma<<<g, 256, DYN>>>(out);
}